// round 15
// baseline (speedup 1.0000x reference)
#include <cuda_runtime.h>
#include <cuda_bf16.h>
#include <cstdint>
#include <math.h>

// GMM score via HMMA (mma.sync bf16), symmetry 2-split GEMM.
//   G[n,(c,j)] = sum_k A_c[j,k] xh_k        (GEMM on xh only; B in hi+lo splits)
//   x^T A x    = sum_j (xh+2*xl)_j G_j  (+ xl^T A xl dropped, ~2^-18)
//   d[n,c]     = quad + sum_j (xh+xl)_j * (-2 b_c[j]) + k_c
//   score      = exp(sum_c w_c log d)
// M=32 per warp: 4-warp CTA (128 samples), 2 CTAs/SM (256 regs/thread budget).
// Each B-fragment feeds 4 HMMA (2 m-tiles x 2 n-tiles) -> half the smem B traffic.

#define ROWB    144           // bytes per smem row (72 bf16, 64 used) — conflict-free ldmatrix
#define XHI_B   18432         // 128 rows * 144
#define HALF_BB 18432
#define CHUNK_B 36864         // hi + lo image of one B chunk

__device__ __align__(16) unsigned char g_B[8][CHUNK_B];
__device__ __align__(16) float g_bm2[1024];   // -2 * b_c[j],  [c*64 + j]
__device__ float g_kc[16];

__device__ __forceinline__ uint32_t smem_u32(const void* p) {
    uint32_t a;
    asm("{ .reg .u64 t; cvta.to.shared.u64 t, %1; cvt.u32.u64 %0, t; }" : "=r"(a) : "l"(p));
    return a;
}
__device__ __forceinline__ uint32_t pk(__nv_bfloat16 a, __nv_bfloat16 b) {
    __nv_bfloat162 t(a, b);
    return *reinterpret_cast<uint32_t*>(&t);
}

#define HMMA(acc, a, b0, b1)                                                  \
    asm volatile("mma.sync.aligned.m16n8k16.row.col.f32.bf16.bf16.f32 "       \
        "{%0,%1,%2,%3},{%4,%5,%6,%7},{%8,%9},{%0,%1,%2,%3};"                  \
        : "+f"((acc)[0]), "+f"((acc)[1]), "+f"((acc)[2]), "+f"((acc)[3])      \
        : "r"((a)[0]), "r"((a)[1]), "r"((a)[2]), "r"((a)[3]), "r"(b0), "r"(b1))

// ---------------- precomp 1: pack B hi/lo + b vectors ----------------
__global__ void precomp1(const float* __restrict__ A, const float* __restrict__ Mn) {
    if (blockIdx.x < 128) {
        const int idx   = blockIdx.x * 256 + threadIdx.x;   // 0..32767
        const int chunk = idx >> 12;
        const int rem   = idx & 4095;
        const int row   = rem >> 5;     // chunk-local col (par*64 + j)
        const int kp    = rem & 31;
        const int comp  = chunk * 2 + (row >> 6);
        const int j     = row & 63;
        const float2 v = *(const float2*)(A + comp * 4096 + j * 64 + kp * 2);
        __nv_bfloat16 h0 = __float2bfloat16(v.x), h1 = __float2bfloat16(v.y);
        __nv_bfloat16 l0 = __float2bfloat16(v.x - __bfloat162float(h0));
        __nv_bfloat16 l1 = __float2bfloat16(v.y - __bfloat162float(h1));
        *(uint32_t*)(g_B[chunk] + row * ROWB + kp * 4)           = pk(h0, h1);
        *(uint32_t*)(g_B[chunk] + HALF_BB + row * ROWB + kp * 4) = pk(l0, l1);
    } else {
        // b_c[j] = A_c[j,:] . m_c
        const int bi = (blockIdx.x - 128) * 256 + threadIdx.x;  // 0..1023
        const int c = bi >> 6, j = bi & 63;
        const float4* Ar = (const float4*)(A + c * 4096 + j * 64);
        const float4* mr = (const float4*)(Mn + c * 64);
        float s0 = 0, s1 = 0, s2 = 0, s3 = 0;
        #pragma unroll
        for (int t = 0; t < 16; t++) {
            float4 a = Ar[t], m = mr[t];
            s0 = fmaf(a.x, m.x, s0); s1 = fmaf(a.y, m.y, s1);
            s2 = fmaf(a.z, m.z, s2); s3 = fmaf(a.w, m.w, s3);
        }
        g_bm2[bi] = -2.0f * ((s0 + s1) + (s2 + s3));
    }
}

// ---------------- precomp 2: k_c = m_c^T b_c ----------------
__global__ void precomp2(const float* __restrict__ Mn) {
    const int c = threadIdx.x;
    if (c < 16) {
        float acc = 0.0f;
        #pragma unroll
        for (int j = 0; j < 64; j++)
            acc = fmaf(Mn[c * 64 + j], -0.5f * g_bm2[c * 64 + j], acc);
        g_kc[c] = acc;
    }
}

// ---------------- main kernel ----------------
// smem: Xhi [0,18432) | 2 x B buf (36864 each) | bm2 4KB | w/kc 128B
#define SM_B0  XHI_B                          // 18432
#define SM_BM  (XHI_B + 2 * CHUNK_B)          // 92160
#define SM_WKC (SM_BM + 4096)                 // 96256
#define SMEM_BYTES (SM_WKC + 128)             // 96384

__global__ void __launch_bounds__(128, 2)
gmm_hmma_kernel(const float* __restrict__ X, const float* __restrict__ W,
                float* __restrict__ out, int N)
{
    extern __shared__ unsigned char smem[];
    const uint32_t sb = smem_u32(smem);
    const int tid  = threadIdx.x;
    const int wid  = tid >> 5;
    const int lane = tid & 31;
    const int base = blockIdx.x * 128;

    // prefetch B chunk 0 (128 threads x 16B x 18 = 36864)
    {
        size_t gsrc = __cvta_generic_to_global(g_B[0]);
        const uint32_t dst = sb + SM_B0;
        #pragma unroll
        for (int i = 0; i < 18; i++) {
            int o = (i * 128 + tid) * 16;
            asm volatile("cp.async.cg.shared.global [%0], [%1], 16;"
                         :: "r"(dst + o), "l"(gsrc + o));
        }
        asm volatile("cp.async.commit_group;");
    }
    if (tid < 16) {
        *(float*)(smem + SM_WKC + 4 * tid)      = W[tid];
        *(float*)(smem + SM_WKC + 64 + 4 * tid) = g_kc[tid];
    }
    // bm2 4KB -> smem (128 threads x 2 float4)
    ((float4*)(smem + SM_BM))[tid]       = ((const float4*)g_bm2)[tid];
    ((float4*)(smem + SM_BM))[tid + 128] = ((const float4*)g_bm2)[tid + 128];

    // stage Xhi: one row per thread
    {
        const float4* xg = (const float4*)(X + (size_t)(base + tid) * 64);
        unsigned char* rp = smem + tid * ROWB;
        #pragma unroll
        for (int q = 0; q < 16; q++) {
            float4 v = xg[q];
            *(uint2*)(rp + q * 8) = make_uint2(
                pk(__float2bfloat16(v.x), __float2bfloat16(v.y)),
                pk(__float2bfloat16(v.z), __float2bfloat16(v.w)));
        }
    }

    const int r0g = wid * 32 + (lane >> 2);   // first of this thread's 4 quad rows
    // epilogue weights: wx = xh + 2*xl (fp32), xlp = xl packed bf16 -> x = wx - xl
    float    wx[4][16];
    uint32_t xlp[4][8];
    {
        #pragma unroll
        for (int rh = 0; rh < 4; rh++) {
            const float* xr = X + (size_t)(base + r0g + rh * 8) * 64 + 2 * (lane & 3);
            #pragma unroll
            for (int q = 0; q < 8; q++) {
                float2 v = *(const float2*)(xr + q * 8);
                __nv_bfloat16 h0 = __float2bfloat16(v.x), h1 = __float2bfloat16(v.y);
                float l0 = v.x - __bfloat162float(h0);
                float l1 = v.y - __bfloat162float(h1);
                wx[rh][2*q]   = __bfloat162float(h0) + 2.0f * l0;
                wx[rh][2*q+1] = __bfloat162float(h1) + 2.0f * l1;
                xlp[rh][q] = pk(__float2bfloat16(l0), __float2bfloat16(l1));
            }
        }
    }
    __syncthreads();

    // A-fragments: 2 m-tiles (rows wid*32 + mt*16 ...), 4 K-steps, Xhi only
    uint32_t Ahi[2][4][4];
    {
        const uint32_t coff = (lane >> 4) * 16;
        #pragma unroll
        for (int mt = 0; mt < 2; mt++) {
            const int arow = wid * 32 + mt * 16 + ((lane >> 3) & 1) * 8 + (lane & 7);
            #pragma unroll
            for (int s = 0; s < 4; s++) {
                uint32_t ah = sb + arow * ROWB + coff + s * 32;
                asm volatile("ldmatrix.sync.aligned.m8n8.x4.shared.b16 {%0,%1,%2,%3}, [%4];"
                    : "=r"(Ahi[mt][s][0]), "=r"(Ahi[mt][s][1]),
                      "=r"(Ahi[mt][s][2]), "=r"(Ahi[mt][s][3]) : "r"(ah));
            }
        }
    }

    float la[4] = {0.f, 0.f, 0.f, 0.f};

    for (int c = 0; c < 8; c++) {
        asm volatile("cp.async.wait_group 0;");  // chunk c resident
        __syncthreads();                          // visible; buf (c+1)&1 free

        if (c + 1 < 8) {
            size_t gsrc = __cvta_generic_to_global(g_B[c + 1]);
            const uint32_t dst = sb + SM_B0 + ((c + 1) & 1) * CHUNK_B;
            #pragma unroll
            for (int i = 0; i < 18; i++) {
                int o = (i * 128 + tid) * 16;
                asm volatile("cp.async.cg.shared.global [%0], [%1], 16;"
                             :: "r"(dst + o), "l"(gsrc + o));
            }
            asm volatile("cp.async.commit_group;");
        }

        const uint32_t Bb = sb + SM_B0 + (c & 1) * CHUNK_B
                          + ((lane >> 4) * 8 + (lane & 7)) * ROWB + ((lane >> 3) & 1) * 16;

        #pragma unroll
        for (int half = 0; half < 2; half++) {
            const int cc = 2 * c + half;
            float acc[2][8][4];
            #pragma unroll
            for (int mt = 0; mt < 2; mt++)
                #pragma unroll
                for (int nt = 0; nt < 8; nt++) {
                    acc[mt][nt][0] = 0.f; acc[mt][nt][1] = 0.f;
                    acc[mt][nt][2] = 0.f; acc[mt][nt][3] = 0.f;
                }

            #pragma unroll
            for (int t2 = 0; t2 < 4; t2++) {
                #pragma unroll
                for (int s = 0; s < 4; s++) {
                    uint32_t bh0, bh1, bh2, bh3, bl0, bl1, bl2, bl3;
                    const uint32_t ab = Bb + (half * 64 + t2 * 16) * ROWB + s * 32;
                    asm volatile("ldmatrix.sync.aligned.m8n8.x4.shared.b16 {%0,%1,%2,%3}, [%4];"
                                 : "=r"(bh0), "=r"(bh1), "=r"(bh2), "=r"(bh3) : "r"(ab));
                    asm volatile("ldmatrix.sync.aligned.m8n8.x4.shared.b16 {%0,%1,%2,%3}, [%4];"
                                 : "=r"(bl0), "=r"(bl1), "=r"(bl2), "=r"(bl3) : "r"(ab + HALF_BB));
                    #pragma unroll
                    for (int mt = 0; mt < 2; mt++) {
                        HMMA(acc[mt][2*t2],   Ahi[mt][s], bh0, bh1);
                        HMMA(acc[mt][2*t2+1], Ahi[mt][s], bh2, bh3);
                        HMMA(acc[mt][2*t2],   Ahi[mt][s], bl0, bl1);
                        HMMA(acc[mt][2*t2+1], Ahi[mt][s], bl2, bl3);
                    }
                }
            }

            // epilogue: linear (exact x = wx - xl) + quad (wx . G), 4 row-groups
            const float* bm = (const float*)(smem + SM_BM) + cc * 64;
            float p[4] = {0.f, 0.f, 0.f, 0.f};
            #pragma unroll
            for (int i = 0; i < 16; i++) {
                const int j = (i >> 1) * 8 + 2 * (lane & 3) + (i & 1);
                const float b = bm[j];
                #pragma unroll
                for (int rh = 0; rh < 4; rh++) {
                    __nv_bfloat162 lp = *reinterpret_cast<__nv_bfloat162*>(&xlp[rh][i >> 1]);
                    const float l = __bfloat162float((i & 1) ? lp.y : lp.x);
                    p[rh] = fmaf(wx[rh][i] - l, b, p[rh]);
                }
            }
            #pragma unroll
            for (int nt = 0; nt < 8; nt++) {
                #pragma unroll
                for (int mt = 0; mt < 2; mt++) {
                    p[2*mt]   = fmaf(wx[2*mt][2*nt],     acc[mt][nt][0], p[2*mt]);
                    p[2*mt]   = fmaf(wx[2*mt][2*nt+1],   acc[mt][nt][1], p[2*mt]);
                    p[2*mt+1] = fmaf(wx[2*mt+1][2*nt],   acc[mt][nt][2], p[2*mt+1]);
                    p[2*mt+1] = fmaf(wx[2*mt+1][2*nt+1], acc[mt][nt][3], p[2*mt+1]);
                }
            }
            const float wc = *(float*)(smem + SM_WKC + 4 * cc);
            const float kc = *(float*)(smem + SM_WKC + 64 + 4 * cc);
            #pragma unroll
            for (int rh = 0; rh < 4; rh++) {
                float v = p[rh];
                v += __shfl_xor_sync(0xFFFFFFFFu, v, 1);
                v += __shfl_xor_sync(0xFFFFFFFFu, v, 2);
                la[rh] = fmaf(wc, __logf(v + kc), la[rh]);
            }
        }
    }

    if ((lane & 3) == 0) {
        #pragma unroll
        for (int rh = 0; rh < 4; rh++)
            out[base + r0g + rh * 8] = __expf(la[rh]);
    }
}

// ---------------- launch ----------------
extern "C" void kernel_launch(void* const* d_in, const int* in_sizes, int n_in,
                              void* d_out, int out_size)
{
    const float* X     = (const float*)d_in[0];   // [N, 64]
    const float* Ainv  = (const float*)d_in[1];   // [16, 64, 64]
    const float* Means = (const float*)d_in[2];   // [16, 64]
    const float* W     = (const float*)d_in[3];   // [16]
    float* out = (float*)d_out;

    const int N = in_sizes[0] / 64;

    cudaFuncSetAttribute(gmm_hmma_kernel, cudaFuncAttributeMaxDynamicSharedMemorySize, SMEM_BYTES);

    precomp1<<<132, 256>>>(Ainv, Means);
    precomp2<<<1, 32>>>(Means);
    gmm_hmma_kernel<<<N / 128, 128, SMEM_BYTES>>>(X, W, out, N);
}